// round 10
// baseline (speedup 1.0000x reference)
#include <cuda_runtime.h>

#define Bn 8
#define Cn 24
#define Mn 960
#define Wn 15                   // real 64-bit words per row (960/64)
#define WS 16                   // padded words per row
#define ROWS (Bn*Mn)            // 7680

typedef unsigned long long u64;

// Padded bitmap planes (word 15 of each row = 0).
// plane order: g_P2[5]=r10, [4]=r9, [3]=r8, [2]=r7, [1]=r6, [0]=r4
__device__ ulonglong2 g_F2[ROWS * 8];
__device__ ulonglong2 g_P2[6][ROWS * 8];
__device__ ulonglong2 g_E2[ROWS * 8];     // eroded bitmap

// ── K1: pack + horizontal erosion (row-local, no halo, DRAM-streaming).
#define PR 16                   // rows per block
__global__ void __launch_bounds__(256) pack_kernel(const float* __restrict__ in) {
    __shared__ u64 sF[PR][Wn];
    const int lane = threadIdx.x & 31;
    const int warp = threadIdx.x >> 5;
    const int row0 = blockIdx.x * PR;                 // global row = b*Mn + y

#pragma unroll
    for (int i = 0; i < PR / 8; i++) {                // 8 warps, 2 rows each
        int rr = warp + (i << 3);
        int row = row0 + rr;
        int b = row / Mn, y = row - b * Mn;
        const float* p = in + ((size_t)(b * Cn + 1) * Mn + y) * Mn + lane;
        float v[30];
#pragma unroll
        for (int j = 0; j < 30; j++) v[j] = p[j * 32];
        unsigned bb[30];
#pragma unroll
        for (int j = 0; j < 30; j++) bb[j] = __ballot_sync(0xffffffffu, v[j] == 0.0f);
        if (lane < Wn) {
            unsigned lo = 0, hi = 0;
#pragma unroll
            for (int k = 0; k < Wn; k++)
                if (lane == k) { lo = bb[2 * k]; hi = bb[2 * k + 1]; }
            sF[rr][lane] = ((u64)hi << 32) | lo;
        }
    }
    __syncthreads();

    // 256 tasks exactly: PR rows x 16 words (word 15 = zero pad)
    int t = threadIdx.x;
    int rr = t >> 4, w = t & 15;
    int i = (row0 + rr) * WS + w;
    u64* Fw = (u64*)g_F2;
    if (w == Wn) {                                    // zero the pad word
        Fw[i] = 0ULL;
#pragma unroll
        for (int p = 0; p < 6; p++) ((u64*)g_P2[p])[i] = 0ULL;
    } else {
        u64 c = sF[rr][w];
        u64 l = (w > 0)      ? sF[rr][w - 1] : 0ULL;
        u64 r = (w < Wn - 1) ? sF[rr][w + 1] : 0ULL;
        Fw[i] = c;
        u64 acc = c;
#pragma unroll
        for (int d = 1; d <= 10; d++) {
            acc &= ((c << d) | (l >> (64 - d))) & ((c >> d) | (r << (64 - d)));
            if (d == 4)       ((u64*)g_P2[0])[i] = acc;
            else if (d == 6)  ((u64*)g_P2[1])[i] = acc;
            else if (d == 7)  ((u64*)g_P2[2])[i] = acc;
            else if (d == 8)  ((u64*)g_P2[3])[i] = acc;
            else if (d == 9)  ((u64*)g_P2[4])[i] = acc;
            else if (d == 10) ((u64*)g_P2[5])[i] = acc;
        }
    }
}

// ── K2: verode — pure streaming, no smem, no barriers. One thread per padded
// word; 21 independent loads at immediate offsets off one base.
__global__ void __launch_bounds__(256) verode_kernel() {
    int t = blockIdx.x * 256 + threadIdx.x;           // 0 .. ROWS*WS-1
    int row = t >> 4;
    int w = t & 15;
    int b = row / Mn, y = row - b * Mn;
    u64 e = 0ULL;
    if (w < Wn && y >= 10 && y <= Mn - 11) {
        size_t i = (size_t)row * WS + w;
        const u64* P4 = (const u64*)g_P2[4];
        const u64* P3 = (const u64*)g_P2[3];
        u64 v0  = ((const u64*)g_P2[5])[i];
        u64 v1  = P4[i - 1*WS];   u64 v2  = P4[i + 1*WS];
        u64 v3  = P4[i - 2*WS];   u64 v4  = P4[i + 2*WS];
        u64 v5  = P4[i - 3*WS];   u64 v6  = P4[i + 3*WS];
        u64 v7  = P4[i - 4*WS];   u64 v8  = P4[i + 4*WS];
        u64 v9  = P3[i - 5*WS];   u64 v10 = P3[i + 5*WS];
        u64 v11 = P3[i - 6*WS];   u64 v12 = P3[i + 6*WS];
        u64 v13 = ((const u64*)g_P2[2])[i - 7*WS];
        u64 v14 = ((const u64*)g_P2[2])[i + 7*WS];
        u64 v15 = ((const u64*)g_P2[1])[i - 8*WS];
        u64 v16 = ((const u64*)g_P2[1])[i + 8*WS];
        u64 v17 = ((const u64*)g_P2[0])[i - 9*WS];
        u64 v18 = ((const u64*)g_P2[0])[i + 9*WS];
        u64 v19 = ((const u64*)g_F2)[i - 10*WS];
        u64 v20 = ((const u64*)g_F2)[i + 10*WS];
        u64 a0 = (v0 & v1) & (v2 & v3);
        u64 a1 = (v4 & v5) & (v6 & v7);
        u64 a2 = (v8 & v9) & (v10 & v11);
        u64 a3 = (v12 & v13) & (v14 & v15);
        u64 a4 = (v16 & v17) & (v18 & v19);
        e = ((a0 & a1) & (a2 & a3)) & (a4 & v20);
    }
    ((u64*)g_E2)[(size_t)row * WS + w] = e;
}

// ── K3: border + float4 expand — warp-autonomous, no smem, no barriers.
// Warp owns 2 consecutive rows; half-warp = one row, lane&15 = word.
__global__ void __launch_bounds__(256) border_kernel(float* __restrict__ out) {
    const unsigned FULL = 0xffffffffu;
    const int lane = threadIdx.x & 31;
    const int wid  = threadIdx.x >> 5;
    const int yo   = (blockIdx.x * 8 + wid) * 2;      // global row base
    const int b    = yo / Mn;
    const int y0   = yo - b * Mn;
    const int half = lane >> 4;
    const int wl   = lane & 15;
    const int y    = y0 + half;                       // this lane's row

    const u64* E = (const u64*)g_E2;
    u64 e = E[(size_t)(b * Mn + y) * WS + wl];        // pad word is stored 0
    int yu = y - 1 < 0 ? 0 : y - 1;                   // clamped rows are zero rows
    int yd = y + 1 > Mn - 1 ? Mn - 1 : y + 1;
    u64 other = __shfl_xor_sync(FULL, e, 16);
    u64 up = half ? other : E[(size_t)(b * Mn + yu) * WS + wl];
    u64 dn = half ? E[(size_t)(b * Mn + yd) * WS + wl] : other;
    u64 lft = __shfl_up_sync(FULL, e, 1);
    u64 rgt = __shfl_down_sync(FULL, e, 1);
    if (wl == 0)  lft = 0ULL;
    if (wl >= 15) rgt = 0ULL;                         // wl=14's right = pad(0) via shfl
    u64 border = (e | up | dn | (e << 1) | (lft >> 63) | (e >> 1) | (rgt << 63)) & ~e;

    // expand: 2 rows x 240 float4 = 480 chunks, 15 per lane, coalesced stores
    float4* o = (float4*)out + (size_t)yo * 240;
#pragma unroll
    for (int k = 0; k < 15; k++) {
        int c  = (k << 5) + lane;                     // 0..479
        int rr = c >= 240;
        int cc = c - rr * 240;
        int src = (rr << 4) + (cc >> 4);              // word index 0..14, never pad
        u64 bw = __shfl_sync(FULL, border, src);
        unsigned nib = (unsigned)(bw >> ((cc & 15) << 2)) & 15u;
        o[(size_t)rr * 240 + cc] =
            make_float4(nib & 1u ? 1.0f : 0.0f, nib & 2u ? 1.0f : 0.0f,
                        nib & 4u ? 1.0f : 0.0f, nib & 8u ? 1.0f : 0.0f);
    }
}

extern "C" void kernel_launch(void* const* d_in, const int* in_sizes, int n_in,
                              void* d_out, int out_size) {
    const float* map_features = (const float*)d_in[0];
    float* out = (float*)d_out;
    pack_kernel<<<ROWS / PR, 256>>>(map_features);    // 480 blocks
    verode_kernel<<<(ROWS * WS) / 256, 256>>>();      // 480 blocks
    border_kernel<<<ROWS / 16, 256>>>(out);           // 480 blocks, 8 warps x 2 rows
}

// round 11
// speedup vs baseline: 1.0644x; 1.0644x over previous
#include <cuda_runtime.h>

#define Bn 8
#define Cn 24
#define Mn 960
#define Wn 15                   // real 64-bit words per row (960/64)
#define WS 16                   // padded words per row
#define ROWS (Bn*Mn)            // 7680

typedef unsigned long long u64;

// Padded bitmap planes (word 15 of each row = 0).
// plane order: g_P2[5]=r10, [4]=r9, [3]=r8, [2]=r7, [1]=r6, [0]=r4
__device__ ulonglong2 g_F2[ROWS * 8];
__device__ ulonglong2 g_P2[6][ROWS * 8];

// ── K1: pack + horizontal erosion (row-local, no halo, DRAM/L2-streaming).
#define PR 16                   // rows per block
__global__ void __launch_bounds__(256) pack_kernel(const float* __restrict__ in) {
    __shared__ u64 sF[PR][Wn];
    const int lane = threadIdx.x & 31;
    const int warp = threadIdx.x >> 5;
    const int row0 = blockIdx.x * PR;                 // global row = b*Mn + y

#pragma unroll
    for (int i = 0; i < PR / 8; i++) {                // 8 warps, 2 rows each
        int rr = warp + (i << 3);
        int row = row0 + rr;
        int b = row / Mn, y = row - b * Mn;
        const float* p = in + ((size_t)(b * Cn + 1) * Mn + y) * Mn + lane;
        float v[30];
#pragma unroll
        for (int j = 0; j < 30; j++) v[j] = p[j * 32];
        unsigned bb[30];
#pragma unroll
        for (int j = 0; j < 30; j++) bb[j] = __ballot_sync(0xffffffffu, v[j] == 0.0f);
        if (lane < Wn) {
            unsigned lo = 0, hi = 0;
#pragma unroll
            for (int k = 0; k < Wn; k++)
                if (lane == k) { lo = bb[2 * k]; hi = bb[2 * k + 1]; }
            sF[rr][lane] = ((u64)hi << 32) | lo;
        }
    }
    __syncthreads();

    // 256 tasks exactly: PR rows x 16 words (word 15 = zero pad)
    int t = threadIdx.x;
    int rr = t >> 4, w = t & 15;
    int i = (row0 + rr) * WS + w;
    u64* Fw = (u64*)g_F2;
    if (w == Wn) {                                    // zero the pad word
        Fw[i] = 0ULL;
#pragma unroll
        for (int p = 0; p < 6; p++) ((u64*)g_P2[p])[i] = 0ULL;
    } else {
        u64 c = sF[rr][w];
        u64 l = (w > 0)      ? sF[rr][w - 1] : 0ULL;
        u64 r = (w < Wn - 1) ? sF[rr][w + 1] : 0ULL;
        Fw[i] = c;
        u64 acc = c;
#pragma unroll
        for (int d = 1; d <= 10; d++) {
            acc &= ((c << d) | (l >> (64 - d))) & ((c >> d) | (r << (64 - d)));
            if (d == 4)       ((u64*)g_P2[0])[i] = acc;
            else if (d == 6)  ((u64*)g_P2[1])[i] = acc;
            else if (d == 7)  ((u64*)g_P2[2])[i] = acc;
            else if (d == 8)  ((u64*)g_P2[3])[i] = acc;
            else if (d == 9)  ((u64*)g_P2[4])[i] = acc;
            else if (d == 10) ((u64*)g_P2[5])[i] = acc;
        }
    }
}

// ── K2: vertical 21-term AND -> border -> LUT float4 expand.
// NT=240 so phase D indexing is loop-constant row + t column (no div/mod),
// and each chunk is LDS+SHF+AND+LDS.128(LUT)+STG.128.
#define RB 8                    // output rows per block; grid = 960
#define NT 240
__global__ void __launch_bounds__(NT, 5) morph_kernel(float* __restrict__ out) {
    __shared__ u64 sE[RB + 2][WS];                    // word 15 zeroed
    __shared__ u64 sB[RB][Wn];
    __shared__ float4 lut[16];
    const int t  = threadIdx.x;
    const int r0 = blockIdx.x * RB;
    const int b  = r0 / Mn;
    const int y0 = r0 - b * Mn;

    if (t < 16)
        lut[t] = make_float4(t & 1 ? 1.0f : 0.0f, t & 2 ? 1.0f : 0.0f,
                             t & 4 ? 1.0f : 0.0f, t & 8 ? 1.0f : 0.0f);

    // Phase B: eroded rows y0-1 .. y0+RB (150 tasks) + zero the 10 pad words.
    if (t < (RB + 2) * Wn) {
        int rr = t / Wn, w = t - rr * Wn;
        int y = y0 + rr - 1;
        u64 e = 0ULL;
        if (y >= 10 && y <= Mn - 11) {
            size_t i = (size_t)(b * Mn + y) * WS + w;
            const u64* P4 = (const u64*)g_P2[4];
            const u64* P3 = (const u64*)g_P2[3];
            u64 v0  = ((const u64*)g_P2[5])[i];
            u64 v1  = P4[i - 1*WS];   u64 v2  = P4[i + 1*WS];
            u64 v3  = P4[i - 2*WS];   u64 v4  = P4[i + 2*WS];
            u64 v5  = P4[i - 3*WS];   u64 v6  = P4[i + 3*WS];
            u64 v7  = P4[i - 4*WS];   u64 v8  = P4[i + 4*WS];
            u64 v9  = P3[i - 5*WS];   u64 v10 = P3[i + 5*WS];
            u64 v11 = P3[i - 6*WS];   u64 v12 = P3[i + 6*WS];
            u64 v13 = ((const u64*)g_P2[2])[i - 7*WS];
            u64 v14 = ((const u64*)g_P2[2])[i + 7*WS];
            u64 v15 = ((const u64*)g_P2[1])[i - 8*WS];
            u64 v16 = ((const u64*)g_P2[1])[i + 8*WS];
            u64 v17 = ((const u64*)g_P2[0])[i - 9*WS];
            u64 v18 = ((const u64*)g_P2[0])[i + 9*WS];
            u64 v19 = ((const u64*)g_F2)[i - 10*WS];
            u64 v20 = ((const u64*)g_F2)[i + 10*WS];
            u64 a0 = (v0 & v1) & (v2 & v3);
            u64 a1 = (v4 & v5) & (v6 & v7);
            u64 a2 = (v8 & v9) & (v10 & v11);
            u64 a3 = (v12 & v13) & (v14 & v15);
            u64 a4 = (v16 & v17) & (v18 & v19);
            e = ((a0 & a1) & (a2 & a3)) & (a4 & v20);
        }
        sE[rr][w] = e;
    } else if (t < (RB + 2) * Wn + (RB + 2)) {
        sE[t - (RB + 2) * Wn][Wn] = 0ULL;             // pad words
    }
    __syncthreads();

    // Phase C: border = dilate(e, cross) & ~e (120 tasks).
    if (t < RB * Wn) {
        int rr = t / Wn, w = t - rr * Wn;
        u64 e  = sE[rr + 1][w];
        u64 eu = sE[rr][w];
        u64 ed = sE[rr + 2][w];
        u64 l  = (w > 0) ? sE[rr + 1][w - 1] : 0ULL;
        u64 r  = sE[rr + 1][w + 1];                   // pad word is 0 at w=14
        u64 d = e | eu | ed | (e << 1) | (l >> 63) | (e >> 1) | (r << 63);
        sB[rr][w] = d & ~e;
    }
    __syncthreads();

    // Phase D: bits -> float4 via LUT; row = loop constant, column = t.
    const int w  = t >> 4;                            // word 0..14, fixed
    const int sh = (t & 15) << 2;                     // nibble shift, fixed
    float4* o = (float4*)out + (size_t)r0 * 240 + t;
#pragma unroll
    for (int k = 0; k < RB; k++) {
        unsigned nib = (unsigned)(sB[k][w] >> sh) & 15u;
        o[(size_t)k * 240] = lut[nib];
    }
}

extern "C" void kernel_launch(void* const* d_in, const int* in_sizes, int n_in,
                              void* d_out, int out_size) {
    const float* map_features = (const float*)d_in[0];
    float* out = (float*)d_out;
    pack_kernel<<<ROWS / PR, 256>>>(map_features);    // 480 blocks
    morph_kernel<<<ROWS / RB, NT>>>(out);             // 960 blocks
}